// round 13
// baseline (speedup 1.0000x reference)
#include <cuda_runtime.h>
#include <cuda_fp16.h>
#include <math.h>

typedef unsigned long long u64;

#define N_NODES 10000
#define N_EDGES 50000
#define NB      500
#define D       64
#define NODE_IN 15
#define EDGE_IN 5
#define EHID    128
#define DDIM    4096   // D*D
#define OUT_DIM 12
#define MP_STEPS 6
#define S2S_STEPS 6

// ---------------- scratch (device globals; no allocation allowed) ----------------
__device__ __align__(16) __half g_We16[(size_t)N_EDGES * DDIM]; // 410 MB fp16
__device__ __align__(16) __half g_hedge16[N_EDGES * EHID];      // 12.8 MB fp16
__device__ __align__(16) __half g_W2h[EHID * DDIM];             // 1 MB fp16
__device__ __align__(16) float g_h[N_NODES * D];                // node state
__device__ __align__(16) float g_agg[N_NODES * D];
// GRU weights (fp16, transposed: [64][192])
__device__ __align__(16) __half g_WihT16[D * 3 * D];
__device__ __align__(16) __half g_WhhT16[D * 3 * D];
// LSTM weights (fp16, transposed: [in][256])
__device__ __align__(16) __half g_L0ihT[2 * D * 4 * D];  // [128][256]
__device__ __align__(16) __half g_L0hhT[D * 4 * D];      // [64][256]
__device__ __align__(16) __half g_L12ihT[2 * D * 4 * D]; // 2 x [64][256]
__device__ __align__(16) __half g_L12hhT[2 * D * 4 * D];

// ---------------- helpers ----------------
__device__ __forceinline__ float sigf(float x) { return 1.f / (1.f + expf(-x)); }
__device__ __forceinline__ unsigned sm_u32(const void* p) {
    return (unsigned)__cvta_generic_to_shared(p);
}
#define LDSM4(r0,r1,r2,r3,addr) \
    asm volatile("ldmatrix.sync.aligned.m8n8.x4.shared.b16 {%0,%1,%2,%3}, [%4];" \
        : "=r"(r0),"=r"(r1),"=r"(r2),"=r"(r3) : "r"(addr))
#define LDSM4T(r0,r1,r2,r3,addr) \
    asm volatile("ldmatrix.sync.aligned.m8n8.x4.trans.shared.b16 {%0,%1,%2,%3}, [%4];" \
        : "=r"(r0),"=r"(r1),"=r"(r2),"=r"(r3) : "r"(addr))
#define MMA16816(d,a,b0,b1) \
    asm volatile("mma.sync.aligned.m16n8k16.row.col.f32.f16.f16.f32 " \
        "{%0,%1,%2,%3}, {%4,%5,%6,%7}, {%8,%9}, {%0,%1,%2,%3};" \
        : "+f"((d)[0]),"+f"((d)[1]),"+f"((d)[2]),"+f"((d)[3]) \
        : "r"((a)[0]),"r"((a)[1]),"r"((a)[2]),"r"((a)[3]), "r"(b0),"r"(b1))
__device__ __forceinline__ void cp16(unsigned d, const void* s, int sz) {
    asm volatile("cp.async.cg.shared.global [%0], [%1], 16, %2;" :: "r"(d), "l"(s), "r"(sz));
}
#define CP_COMMIT() asm volatile("cp.async.commit_group;")
#define CP_WAIT(n)  asm volatile("cp.async.wait_group %0;" :: "n"(n))

// ---------------- prep: transpose small weight matrices + fp16 conversions ---------------
__global__ void k_prep(const float* __restrict__ gWih, const float* __restrict__ gWhh,
                       const float* __restrict__ l0ih, const float* __restrict__ l0hh,
                       const float* __restrict__ l12ih, const float* __restrict__ l12hh,
                       const float* __restrict__ W2) {
    int tid = blockIdx.x * blockDim.x + threadIdx.x;
    int nt  = gridDim.x * blockDim.x;
    for (int x = tid; x < 192 * 64; x += nt) {
        int j = x / 64, i = x % 64;
        g_WihT16[i * 192 + j] = __float2half(gWih[j * 64 + i]);
        g_WhhT16[i * 192 + j] = __float2half(gWhh[j * 64 + i]);
    }
    for (int x = tid; x < 256 * 128; x += nt) {
        int j = x / 128, i = x % 128;
        g_L0ihT[i * 256 + j] = __float2half(l0ih[j * 128 + i]);
    }
    for (int x = tid; x < 256 * 64; x += nt) {
        int j = x / 64, i = x % 64;
        g_L0hhT[i * 256 + j] = __float2half(l0hh[j * 64 + i]);
    }
    for (int x = tid; x < 2 * 256 * 64; x += nt) {
        int l = x / 16384, rem = x % 16384;
        int j = rem / 64, i = rem % 64;
        g_L12ihT[l * 16384 + i * 256 + j] = __float2half(l12ih[l * 16384 + j * 64 + i]);
        g_L12hhT[l * 16384 + i * 256 + j] = __float2half(l12hh[l * 16384 + j * 64 + i]);
    }
    for (int x = tid; x < EHID * DDIM; x += nt)
        g_W2h[x] = __float2half(W2[x]);
}

// ---------------- lin0 + agg init: out = relu(nf @ lin0_W + b); agg = conv_bias --------
__global__ void k_lin0(const float* __restrict__ nf, const float* __restrict__ W,
                       const float* __restrict__ b, const float* __restrict__ cb) {
    int idx = blockIdx.x * 256 + threadIdx.x;   // exactly N_NODES*64
    int n = idx >> 6, d = idx & 63;
    float acc = b[d];
#pragma unroll
    for (int i = 0; i < NODE_IN; i++) acc += nf[n * NODE_IN + i] * W[i * 64 + d];
    g_h[idx] = fmaxf(acc, 0.f);
    g_agg[idx] = cb[d];
}

// ---------------- edge hidden (fp16 out): h = relu(edge_feat @ W1 + b1) ----------------
__global__ void k_edgehid(const float* __restrict__ ef, const float* __restrict__ W1,
                          const float* __restrict__ b1) {
    int idx = blockIdx.x * 256 + threadIdx.x;   // exactly N_EDGES*128
    int e = idx >> 7, k = idx & 127;
    float acc = b1[k];
#pragma unroll
    for (int i = 0; i < EDGE_IN; i++) acc += ef[e * EDGE_IN + i] * W1[i * EHID + k];
    g_hedge16[idx] = __float2half(fmaxf(acc, 0.f));
}

// ---------------- big GEMM via HMMA: block 128x256, warp 64x64, cp.async 2-stage --------
#define BM 128
#define BN 256
#define BK 32
__global__ __launch_bounds__(256) void k_gemm(const float* __restrict__ b2) {
    __shared__ __half As[2][BM * BK];   // 2 x 8 KB, chunk-swizzled (4 chunks/row)
    __shared__ __half Bs[2][BK * BN];   // 2 x 16 KB, chunk-swizzled (32 chunks/row)
    const int tid = threadIdx.x;
    const int wid = tid >> 5, lane = tid & 31;
    const int warp_m = wid & 1, warp_n = wid >> 1;   // 2 x 4 warps
    const int e0 = blockIdx.y * BM;
    const int j0 = blockIdx.x * BN;
    const int li = lane & 7, grp = lane >> 3;
    const unsigned As_b = sm_u32(As), Bs_b = sm_u32(Bs);

    const int a_row0 = tid >> 2, a_ck = tid & 3;     // + 64 rows for second A chunk
    const int b_row0 = tid >> 5, b_ck = tid & 31;    // + 8,16,24 rows for B chunks

    float acc[4][8][4];
#pragma unroll
    for (int f = 0; f < 4; f++)
#pragma unroll
        for (int j = 0; j < 8; j++)
#pragma unroll
            for (int q = 0; q < 4; q++) acc[f][j][q] = 0.f;

#define ISSUE_STAGE(kb, st) do {                                                   \
    _Pragma("unroll")                                                              \
    for (int l = 0; l < 2; l++) {                                                  \
        int row = a_row0 + l * 64;                                                 \
        int e = e0 + row;                                                          \
        unsigned dsta = As_b + (st) * 8192 +                                       \
            (((row << 2) + (a_ck ^ (row & 3))) * 16);                              \
        cp16(dsta, g_hedge16 + (size_t)e * 128 + (kb) * 32 + a_ck * 8,             \
             (e < N_EDGES) ? 16 : 0);                                              \
    }                                                                              \
    _Pragma("unroll")                                                              \
    for (int l = 0; l < 4; l++) {                                                  \
        int row = b_row0 + l * 8;                                                  \
        int cks = (b_ck & 24) | ((b_ck & 7) ^ (row & 7));                          \
        unsigned dstb = Bs_b + (st) * 16384 + (((row << 5) + cks) * 16);           \
        cp16(dstb, g_W2h + (size_t)((kb) * 32 + row) * 4096 + j0 + b_ck * 8, 16);  \
    }                                                                              \
    CP_COMMIT();                                                                   \
} while (0)

    ISSUE_STAGE(0, 0);
#pragma unroll
    for (int kb = 0; kb < 4; kb++) {
        if (kb < 3) { ISSUE_STAGE(kb + 1, (kb + 1) & 1); CP_WAIT(1); }
        else        { CP_WAIT(0); }
        __syncthreads();
        const unsigned Abase = As_b + (kb & 1) * 8192;
        const unsigned Bbase = Bs_b + (kb & 1) * 16384;
#pragma unroll
        for (int s = 0; s < 2; s++) {
            unsigned a[4][4];
#pragma unroll
            for (int f = 0; f < 4; f++) {
                int m0 = warp_m * 64 + f * 16;
                int row = m0 + li + (grp & 1) * 8;
                int ck = (s * 2 + (grp >> 1)) ^ (row & 3);
                LDSM4(a[f][0], a[f][1], a[f][2], a[f][3],
                      Abase + ((row << 2) + ck) * 16);
            }
            unsigned b[4][4];
#pragma unroll
            for (int p = 0; p < 4; p++) {
                int row = s * 16 + li + (grp & 1) * 8;
                int c = warp_n * 8 + p * 2 + (grp >> 1);
                int cks = (c & 24) | ((c & 7) ^ (row & 7));
                LDSM4T(b[p][0], b[p][1], b[p][2], b[p][3],
                       Bbase + ((row << 5) + cks) * 16);
            }
#pragma unroll
            for (int f = 0; f < 4; f++)
#pragma unroll
                for (int p = 0; p < 4; p++) {
                    MMA16816(acc[f][p * 2],     a[f], b[p][0], b[p][1]);
                    MMA16816(acc[f][p * 2 + 1], a[f], b[p][2], b[p][3]);
                }
        }
        __syncthreads();
    }
    // epilogue: + bias, fp16, 4B coalesced stores
#pragma unroll
    for (int j = 0; j < 8; j++) {
        int cn = warp_n * 64 + j * 8 + (lane & 3) * 2;
        float bv0 = b2[j0 + cn], bv1 = b2[j0 + cn + 1];
#pragma unroll
        for (int f = 0; f < 4; f++) {
            int r = warp_m * 64 + f * 16 + (lane >> 2);
            int e = e0 + r;
            if (e < N_EDGES) {
                __half2 h = __floats2half2_rn(acc[f][j][0] + bv0, acc[f][j][1] + bv1);
                *(__half2*)(g_We16 + (size_t)e * 4096 + j0 + cn) = h;
            }
            if (e + 8 < N_EDGES) {
                __half2 h = __floats2half2_rn(acc[f][j][2] + bv0, acc[f][j][3] + bv1);
                *(__half2*)(g_We16 + (size_t)(e + 8) * 4096 + j0 + cn) = h;
            }
        }
    }
}

// ---------------- einsum + scatter: warp per edge, streaming uint4 loads ---------------
__global__ void k_einsum(const int* __restrict__ src, const int* __restrict__ dst) {
    __shared__ float xs[8][64];
    int w = threadIdx.x >> 5, t = threadIdx.x & 31;
    int e = (blockIdx.x << 3) + w;              // exactly N_EDGES
    int s = src[e];
    int j2 = t << 1;
    float2 v = *(const float2*)(g_h + s * 64 + j2);
    xs[w][j2] = v.x; xs[w][j2 + 1] = v.y;
    __syncwarp();
    const uint4* __restrict__ W4 = (const uint4*)(g_We16 + (size_t)e * 4096);
    const int cg = t & 7, rg = t >> 3;
    float acc[8];
#pragma unroll
    for (int k = 0; k < 8; k++) acc[k] = 0.f;
#pragma unroll
    for (int i = 0; i < 16; i++) {
        int r = i * 4 + rg;
        uint4 q = __ldcs(W4 + r * 8 + cg);
        float xi = xs[w][r];
        float2 f0 = __half22float2(*(__half2*)&q.x);
        float2 f1 = __half22float2(*(__half2*)&q.y);
        float2 f2 = __half22float2(*(__half2*)&q.z);
        float2 f3 = __half22float2(*(__half2*)&q.w);
        acc[0] = fmaf(xi, f0.x, acc[0]); acc[1] = fmaf(xi, f0.y, acc[1]);
        acc[2] = fmaf(xi, f1.x, acc[2]); acc[3] = fmaf(xi, f1.y, acc[3]);
        acc[4] = fmaf(xi, f2.x, acc[4]); acc[5] = fmaf(xi, f2.y, acc[5]);
        acc[6] = fmaf(xi, f3.x, acc[6]); acc[7] = fmaf(xi, f3.y, acc[7]);
    }
#pragma unroll
    for (int k = 0; k < 8; k++) {
        acc[k] += __shfl_xor_sync(0xffffffffu, acc[k], 8);
        acc[k] += __shfl_xor_sync(0xffffffffu, acc[k], 16);
    }
    int dn = dst[e];
    int k0 = rg * 2;
    int col = cg * 8 + k0;
    atomicAdd(g_agg + dn * 64 + col,     acc[k0]);
    atomicAdd(g_agg + dn * 64 + col + 1, acc[k0 + 1]);
}

// ---------------- GRU cell: smem-cached fp16 weights, 32 nodes/block (4 per warp) -------
__global__ __launch_bounds__(256) void k_gru(const float* __restrict__ bih,
                                             const float* __restrict__ bhh,
                                             const float* __restrict__ cb) {
    __shared__ __half2 sW[64 * 96];   // 24 KB  Wih^T [64][192] as half2 pairs
    __shared__ __half2 sU[64 * 96];   // 24 KB  Whh^T
    const int tid = threadIdx.x;
    {
        const uint4* gw = (const uint4*)g_WihT16;
        const uint4* gu = (const uint4*)g_WhhT16;
        uint4* dw = (uint4*)sW;
        uint4* du = (uint4*)sU;
        for (int i = tid; i < 1536; i += 256) { dw[i] = gw[i]; du[i] = gu[i]; }
    }
    __syncthreads();
    const int w = tid >> 5, t = tid & 31;
    const int j = t << 1;
#pragma unroll
    for (int it = 0; it < 4; it++) {
        const int n = blockIdx.x * 32 + (w << 2) + it;
        if (n >= N_NODES) break;                 // uniform per warp
        float2 av = *(const float2*)(g_agg + n * 64 + j);
        float2 x2; x2.x = fmaxf(av.x, 0.f); x2.y = fmaxf(av.y, 0.f);
        float2 hv = *(const float2*)(g_h + n * 64 + j);
        *(float2*)(g_agg + n * 64 + j) = *(const float2*)(cb + j);   // reset for next step

        float rx0 = 0.f, rx1 = 0.f, zx0 = 0.f, zx1 = 0.f, nx0 = 0.f, nx1 = 0.f;
        float rh0 = 0.f, rh1 = 0.f, zh0 = 0.f, zh1 = 0.f, nh0 = 0.f, nh1 = 0.f;
#pragma unroll
        for (int i = 0; i < 64; i++) {
            float xi = __shfl_sync(0xffffffffu, (i & 1) ? x2.y : x2.x, i >> 1);
            float hi = __shfl_sync(0xffffffffu, (i & 1) ? hv.y : hv.x, i >> 1);
            float2 wr = __half22float2(sW[i * 96 + t]);
            float2 wz = __half22float2(sW[i * 96 + 32 + t]);
            float2 wn = __half22float2(sW[i * 96 + 64 + t]);
            float2 ur = __half22float2(sU[i * 96 + t]);
            float2 uz = __half22float2(sU[i * 96 + 32 + t]);
            float2 un = __half22float2(sU[i * 96 + 64 + t]);
            rx0 = fmaf(xi, wr.x, rx0); rx1 = fmaf(xi, wr.y, rx1);
            zx0 = fmaf(xi, wz.x, zx0); zx1 = fmaf(xi, wz.y, zx1);
            nx0 = fmaf(xi, wn.x, nx0); nx1 = fmaf(xi, wn.y, nx1);
            rh0 = fmaf(hi, ur.x, rh0); rh1 = fmaf(hi, ur.y, rh1);
            zh0 = fmaf(hi, uz.x, zh0); zh1 = fmaf(hi, uz.y, zh1);
            nh0 = fmaf(hi, un.x, nh0); nh1 = fmaf(hi, un.y, nh1);
        }
        float r0 = sigf(rx0 + bih[j]         + rh0 + bhh[j]);
        float r1 = sigf(rx1 + bih[j + 1]     + rh1 + bhh[j + 1]);
        float z0 = sigf(zx0 + bih[64 + j]    + zh0 + bhh[64 + j]);
        float z1 = sigf(zx1 + bih[64 + j + 1]+ zh1 + bhh[64 + j + 1]);
        float n0 = tanhf(nx0 + bih[128 + j]     + r0 * (nh0 + bhh[128 + j]));
        float n1 = tanhf(nx1 + bih[128 + j + 1] + r1 * (nh1 + bhh[128 + j + 1]));
        float2 o;
        o.x = (1.f - z0) * n0 + z0 * hv.x;
        o.y = (1.f - z1) * n1 + z1 * hv.y;
        *(float2*)(g_h + n * 64 + j) = o;
    }
}

// ---------------- fused Set2Set + head: 4 graphs per block ----------------
__global__ __launch_bounds__(256) void k_set2set(
        const int* __restrict__ gid,
        const float* __restrict__ l0_bih, const float* __restrict__ l0_bhh,
        const float* __restrict__ l12_bih, const float* __restrict__ l12_bhh,
        const float* __restrict__ lin1_W, const float* __restrict__ lin1_b,
        const float* __restrict__ lin2_W, const float* __restrict__ lin2_b,
        float* __restrict__ out) {
    __shared__ float gsh[4][256];
    __shared__ float hst[3][4][64], cst[3][4][64];
    __shared__ float qstar[4][128];
    __shared__ float m2[4][2], s2[4][2];
    __shared__ float r2[4][2][64];
    __shared__ float t1s[4][64];
    __shared__ int rng[4][2];

    const int b0 = blockIdx.x * 4;          // 125 blocks x 4 graphs
    const int tid = threadIdx.x;
    const int wid = tid >> 5, lane = tid & 31;
    const int tg = tid >> 6, tc = tid & 63; // graph/channel split of 256 threads

    if (tid < 8) {
        int g = tid >> 1;
        int target = b0 + g + (tid & 1);
        int lo = 0, hi = N_NODES;
        while (lo < hi) { int mid = (lo + hi) >> 1; if (gid[mid] < target) lo = mid + 1; else hi = mid; }
        rng[g][tid & 1] = lo;
    }
    for (int x = tid; x < 512; x += 256) qstar[x >> 7][x & 127] = 0.f;
#pragma unroll
    for (int l = 0; l < 3; l++) { hst[l][tg][tc] = 0.f; cst[l][tg][tc] = 0.f; }
    __syncthreads();

    for (int step = 0; step < S2S_STEPS; step++) {
        // ---- 3 LSTM layers, weight loads shared across 4 graphs ----
#pragma unroll
        for (int l = 0; l < 3; l++) {
            const __half* WT; const __half* UT; const float* bi; const float* bh;
            const float* x0; const float* x1; const float* x2; const float* x3; int in_dim;
            if (l == 0) {
                WT = g_L0ihT; UT = g_L0hhT; bi = l0_bih; bh = l0_bhh; in_dim = 128;
                x0 = qstar[0]; x1 = qstar[1]; x2 = qstar[2]; x3 = qstar[3];
            } else {
                WT = g_L12ihT + (l - 1) * 16384; UT = g_L12hhT + (l - 1) * 16384;
                bi = l12_bih + (l - 1) * 256; bh = l12_bhh + (l - 1) * 256; in_dim = 64;
                x0 = hst[l - 1][0]; x1 = hst[l - 1][1]; x2 = hst[l - 1][2]; x3 = hst[l - 1][3];
            }
            float bb = bi[tid] + bh[tid];
            float a0 = bb, a1 = bb, a2 = bb, a3 = bb;
#pragma unroll 4
            for (int i = 0; i < in_dim; i++) {
                float wv = __half2float(WT[i * 256 + tid]);
                a0 = fmaf(x0[i], wv, a0); a1 = fmaf(x1[i], wv, a1);
                a2 = fmaf(x2[i], wv, a2); a3 = fmaf(x3[i], wv, a3);
            }
#pragma unroll 4
            for (int i = 0; i < 64; i++) {
                float uv = __half2float(UT[i * 256 + tid]);
                a0 = fmaf(hst[l][0][i], uv, a0); a1 = fmaf(hst[l][1][i], uv, a1);
                a2 = fmaf(hst[l][2][i], uv, a2); a3 = fmaf(hst[l][3][i], uv, a3);
            }
            gsh[0][tid] = a0; gsh[1][tid] = a1; gsh[2][tid] = a2; gsh[3][tid] = a3;
            __syncthreads();
            {
                float ig = sigf(gsh[tg][tc]);
                float fg = sigf(gsh[tg][64 + tc]);
                float gg = tanhf(gsh[tg][128 + tc]);
                float og = sigf(gsh[tg][192 + tc]);
                float cc = fg * cst[l][tg][tc] + ig * gg;
                cst[l][tg][tc] = cc;
                hst[l][tg][tc] = og * tanhf(cc);
            }
            __syncthreads();
        }
        // ---- attention: 2 warps per graph, streaming softmax ----
        const int gg = wid >> 1, sub = wid & 1;
        const int ns = rng[gg][0], ne = rng[gg][1];
        float qa = hst[2][gg][lane], qb = hst[2][gg][32 + lane];
        float m = -INFINITY, ssum = 0.f, r0 = 0.f, r1 = 0.f;
        for (int n = ns + sub; n < ne; n += 2) {
            float o0 = g_h[n * 64 + lane];
            float o1 = g_h[n * 64 + 32 + lane];
            float part = o0 * qa + o1 * qb;
#pragma unroll
            for (int o = 16; o; o >>= 1) part += __shfl_xor_sync(0xffffffffu, part, o);
            if (part > m) {
                float sc = expf(m - part);
                ssum = ssum * sc + 1.f;
                r0 = r0 * sc + o0;
                r1 = r1 * sc + o1;
                m = part;
            } else {
                float wg = expf(part - m);
                ssum += wg;
                r0 += wg * o0;
                r1 += wg * o1;
            }
        }
        if (lane == 0) { m2[gg][sub] = m; s2[gg][sub] = ssum; }
        r2[gg][sub][lane] = r0;
        r2[gg][sub][32 + lane] = r1;
        __syncthreads();
        {
            float M = -INFINITY;
#pragma unroll
            for (int p = 0; p < 2; p++) if (s2[tg][p] > 0.f) M = fmaxf(M, m2[tg][p]);
            float S = 0.f, R = 0.f;
#pragma unroll
            for (int p = 0; p < 2; p++) {
                if (s2[tg][p] > 0.f) {
                    float sc = expf(m2[tg][p] - M);
                    S += s2[tg][p] * sc;
                    R += r2[tg][p][tc] * sc;
                }
            }
            qstar[tg][tc] = hst[2][tg][tc];
            qstar[tg][64 + tc] = (S > 0.f) ? (R / S) : 0.f;
        }
        __syncthreads();
    }
    // ---- head: t1 = relu(qstar @ lin1 + b1); out = t1 @ lin2 + b2 ----
    {
        float acc = lin1_b[tc];
#pragma unroll 4
        for (int i = 0; i < 128; i++) acc = fmaf(qstar[tg][i], lin1_W[i * 64 + tc], acc);
        t1s[tg][tc] = fmaxf(acc, 0.f);
    }
    __syncthreads();
    if (tid < 4 * OUT_DIM) {
        int g = tid / OUT_DIM, o = tid % OUT_DIM;
        float acc = lin2_b[o];
#pragma unroll 4
        for (int d = 0; d < 64; d++) acc = fmaf(t1s[g][d], lin2_W[d * OUT_DIM + o], acc);
        out[(b0 + g) * OUT_DIM + o] = acc;
    }
}

// ---------------- launcher ----------------
extern "C" void kernel_launch(void* const* d_in, const int* in_sizes, int n_in,
                              void* d_out, int out_size) {
    const float* node_feat = (const float*)d_in[0];
    const float* edge_feat = (const float*)d_in[1];
    const int*   src       = (const int*)d_in[2];
    const int*   dst       = (const int*)d_in[3];
    const int*   gid       = (const int*)d_in[4];
    // d_in[5] = num_graphs (unused; B fixed)
    const float* lin0_W = (const float*)d_in[6];
    const float* lin0_b = (const float*)d_in[7];
    const float* em_W1  = (const float*)d_in[8];
    const float* em_b1  = (const float*)d_in[9];
    const float* em_W2  = (const float*)d_in[10];
    const float* em_b2  = (const float*)d_in[11];
    const float* conv_bias = (const float*)d_in[12];
    const float* gru_Wih = (const float*)d_in[13];
    const float* gru_Whh = (const float*)d_in[14];
    const float* gru_bih = (const float*)d_in[15];
    const float* gru_bhh = (const float*)d_in[16];
    const float* l0_Wih = (const float*)d_in[17];
    const float* l0_Whh = (const float*)d_in[18];
    const float* l0_bih = (const float*)d_in[19];
    const float* l0_bhh = (const float*)d_in[20];
    const float* l12_Wih = (const float*)d_in[21];
    const float* l12_Whh = (const float*)d_in[22];
    const float* l12_bih = (const float*)d_in[23];
    const float* l12_bhh = (const float*)d_in[24];
    const float* lin1_W = (const float*)d_in[25];
    const float* lin1_b = (const float*)d_in[26];
    const float* lin2_W = (const float*)d_in[27];
    const float* lin2_b = (const float*)d_in[28];
    float* out = (float*)d_out;

    (void)in_sizes; (void)n_in; (void)out_size;

    k_prep<<<128, 256>>>(gru_Wih, gru_Whh, l0_Wih, l0_Whh, l12_Wih, l12_Whh, em_W2);
    k_lin0<<<(N_NODES * 64) / 256, 256>>>(node_feat, lin0_W, lin0_b, conv_bias);
    k_edgehid<<<(N_EDGES * EHID) / 256, 256>>>(edge_feat, em_W1, em_b1);
    k_gemm<<<dim3(DDIM / BN, (N_EDGES + BM - 1) / BM), 256>>>(em_b2);

    for (int s = 0; s < MP_STEPS; s++) {
        k_einsum<<<N_EDGES / 8, 256>>>(src, dst);
        k_gru<<<(N_NODES + 31) / 32, 256>>>(gru_bih, gru_bhh, conv_bias);
    }

    k_set2set<<<125, 256>>>(gid, l0_bih, l0_bhh, l12_bih, l12_bhh,
                            lin1_W, lin1_b, lin2_W, lin2_b, out);
}

// round 16
// speedup vs baseline: 2.3506x; 2.3506x over previous
#include <cuda_runtime.h>
#include <cuda_fp16.h>
#include <math.h>

typedef unsigned long long u64;

#define N_NODES 10000
#define N_EDGES 50000
#define NB      500
#define D       64
#define NODE_IN 15
#define EDGE_IN 5
#define EHID    128
#define DDIM    4096   // D*D
#define OUT_DIM 12
#define MP_STEPS 6
#define S2S_STEPS 6

// ---------------- scratch (device globals; no allocation allowed) ----------------
__device__ __align__(16) __half g_We16[(size_t)N_EDGES * DDIM]; // 410 MB fp16
__device__ __align__(16) __half g_hedge16[N_EDGES * EHID];      // 12.8 MB fp16
__device__ __align__(16) __half g_W2h[EHID * DDIM];             // 1 MB fp16
__device__ __align__(16) float g_h[N_NODES * D];                // node state
__device__ __align__(16) float g_agg[N_NODES * D];
// GRU weights (fp16, transposed: [64][192])
__device__ __align__(16) __half g_WihT16[D * 3 * D];
__device__ __align__(16) __half g_WhhT16[D * 3 * D];
// LSTM weights (fp16, transposed: [in][256])
__device__ __align__(16) __half g_L0ihT[2 * D * 4 * D];  // [128][256]
__device__ __align__(16) __half g_L0hhT[D * 4 * D];      // [64][256]
__device__ __align__(16) __half g_L12ihT[2 * D * 4 * D]; // 2 x [64][256]
__device__ __align__(16) __half g_L12hhT[2 * D * 4 * D];

// ---------------- helpers ----------------
__device__ __forceinline__ float sigf(float x) { return 1.f / (1.f + expf(-x)); }
__device__ __forceinline__ unsigned sm_u32(const void* p) {
    return (unsigned)__cvta_generic_to_shared(p);
}
#define LDSM4(r0,r1,r2,r3,addr) \
    asm volatile("ldmatrix.sync.aligned.m8n8.x4.shared.b16 {%0,%1,%2,%3}, [%4];" \
        : "=r"(r0),"=r"(r1),"=r"(r2),"=r"(r3) : "r"(addr))
#define LDSM4T(r0,r1,r2,r3,addr) \
    asm volatile("ldmatrix.sync.aligned.m8n8.x4.trans.shared.b16 {%0,%1,%2,%3}, [%4];" \
        : "=r"(r0),"=r"(r1),"=r"(r2),"=r"(r3) : "r"(addr))
#define MMA16816(d,a,b0,b1) \
    asm volatile("mma.sync.aligned.m16n8k16.row.col.f32.f16.f16.f32 " \
        "{%0,%1,%2,%3}, {%4,%5,%6,%7}, {%8,%9}, {%0,%1,%2,%3};" \
        : "+f"((d)[0]),"+f"((d)[1]),"+f"((d)[2]),"+f"((d)[3]) \
        : "r"((a)[0]),"r"((a)[1]),"r"((a)[2]),"r"((a)[3]), "r"(b0),"r"(b1))
__device__ __forceinline__ void cp16(unsigned d, const void* s, int sz) {
    asm volatile("cp.async.cg.shared.global [%0], [%1], 16, %2;" :: "r"(d), "l"(s), "r"(sz));
}
#define CP_COMMIT() asm volatile("cp.async.commit_group;")
#define CP_WAIT(n)  asm volatile("cp.async.wait_group %0;" :: "n"(n))

// ---------------- prep: transpose small weight matrices + fp16 conversions ---------------
__global__ void k_prep(const float* __restrict__ gWih, const float* __restrict__ gWhh,
                       const float* __restrict__ l0ih, const float* __restrict__ l0hh,
                       const float* __restrict__ l12ih, const float* __restrict__ l12hh,
                       const float* __restrict__ W2) {
    int tid = blockIdx.x * blockDim.x + threadIdx.x;
    int nt  = gridDim.x * blockDim.x;
    for (int x = tid; x < 192 * 64; x += nt) {
        int j = x / 64, i = x % 64;
        g_WihT16[i * 192 + j] = __float2half(gWih[j * 64 + i]);
        g_WhhT16[i * 192 + j] = __float2half(gWhh[j * 64 + i]);
    }
    for (int x = tid; x < 256 * 128; x += nt) {
        int j = x / 128, i = x % 128;
        g_L0ihT[i * 256 + j] = __float2half(l0ih[j * 128 + i]);
    }
    for (int x = tid; x < 256 * 64; x += nt) {
        int j = x / 64, i = x % 64;
        g_L0hhT[i * 256 + j] = __float2half(l0hh[j * 64 + i]);
    }
    for (int x = tid; x < 2 * 256 * 64; x += nt) {
        int l = x / 16384, rem = x % 16384;
        int j = rem / 64, i = rem % 64;
        g_L12ihT[l * 16384 + i * 256 + j] = __float2half(l12ih[l * 16384 + j * 64 + i]);
        g_L12hhT[l * 16384 + i * 256 + j] = __float2half(l12hh[l * 16384 + j * 64 + i]);
    }
    for (int x = tid; x < EHID * DDIM; x += nt)
        g_W2h[x] = __float2half(W2[x]);
}

// ---------------- lin0 + agg init: out = relu(nf @ lin0_W + b); agg = conv_bias --------
__global__ void k_lin0(const float* __restrict__ nf, const float* __restrict__ W,
                       const float* __restrict__ b, const float* __restrict__ cb) {
    int idx = blockIdx.x * 256 + threadIdx.x;   // exactly N_NODES*64
    int n = idx >> 6, d = idx & 63;
    float acc = b[d];
#pragma unroll
    for (int i = 0; i < NODE_IN; i++) acc += nf[n * NODE_IN + i] * W[i * 64 + d];
    g_h[idx] = fmaxf(acc, 0.f);
    g_agg[idx] = cb[d];
}

// ---------------- edge hidden (fp16 out): h = relu(edge_feat @ W1 + b1) ----------------
__global__ void k_edgehid(const float* __restrict__ ef, const float* __restrict__ W1,
                          const float* __restrict__ b1) {
    int idx = blockIdx.x * 256 + threadIdx.x;   // exactly N_EDGES*128
    int e = idx >> 7, k = idx & 127;
    float acc = b1[k];
#pragma unroll
    for (int i = 0; i < EDGE_IN; i++) acc += ef[e * EDGE_IN + i] * W1[i * EHID + k];
    g_hedge16[idx] = __float2half(fmaxf(acc, 0.f));
}

// ---------------- persistent-column GEMM via HMMA ----------------
// Each CTA: one 256-col N column (B column resident in smem, 64 KB, loaded once)
// x strip of 17 M-tiles (128 edges each), A double-buffered via cp.async (2x32 KB).
// 8 warps as 2(M) x 4(N); warp tile 64x64. Dynamic smem = 128 KB.
#define BM_ 128
#define NTILE_M 391     // ceil(50000/128)
#define NSTRIP  23      // 23*17 = 391 exactly
#define TPS     17
__global__ __launch_bounds__(256) void k_gemm(const float* __restrict__ b2) {
    extern __shared__ __half dsm[];
    __half* Bs = dsm;               // 128 x 256 halves = 64 KB (swizzled)
    __half* As = dsm + 32768;       // 2 stages x (128 x 128 halves = 32 KB)
    const int tid = threadIdx.x;
    const int wid = tid >> 5, lane = tid & 31;
    const int warp_m = wid & 1, warp_n = wid >> 1;
    const int j0 = blockIdx.x * 256;
    const int li = lane & 7, grp = lane >> 3;
    const unsigned Bs_b = sm_u32(Bs), As_b = sm_u32(As);

    // ---- B column load (once): 128 rows x 32 chunks of 16B, 3-bit XOR swizzle ----
#pragma unroll
    for (int l = 0; l < 16; l++) {
        int cid = tid + l * 256;
        int row = cid >> 5, ck = cid & 31;
        int cks = (ck & 24) | ((ck & 7) ^ (row & 7));
        cp16(Bs_b + ((row << 5) + cks) * 16,
             g_W2h + (size_t)row * 4096 + j0 + ck * 8, 16);
    }
    CP_COMMIT();

    const int t0 = blockIdx.y * TPS;
    const int tend = (t0 + TPS < NTILE_M) ? (t0 + TPS) : NTILE_M;

#define ISSUE_A(tt, st) do {                                                     \
    int ebase = (tt) * BM_;                                                      \
    _Pragma("unroll")                                                            \
    for (int l = 0; l < 8; l++) {                                                \
        int cid = tid + l * 256;                                                 \
        int row = cid >> 4, ck = cid & 15;                                       \
        int e = ebase + row;                                                     \
        int cks = (ck & 8) | ((ck & 7) ^ (row & 7));                             \
        cp16(As_b + (st) * 32768 + (((row << 4) + cks) * 16),                    \
             g_hedge16 + (size_t)e * 128 + ck * 8, (e < N_EDGES) ? 16 : 0);      \
    }                                                                            \
    CP_COMMIT();                                                                 \
} while (0)

    // hoist bias values (constant per CTA column)
    float bv[8][2];
#pragma unroll
    for (int j = 0; j < 8; j++) {
        int cn = warp_n * 64 + j * 8 + (lane & 3) * 2;
        bv[j][0] = b2[j0 + cn];
        bv[j][1] = b2[j0 + cn + 1];
    }

    ISSUE_A(t0, 0);
    float acc[4][8][4];

    for (int t = t0; t < tend; t++) {
        const int st = (t - t0) & 1;
        if (t + 1 < tend) { ISSUE_A(t + 1, st ^ 1); CP_WAIT(1); }
        else              { CP_WAIT(0); }
        __syncthreads();

#pragma unroll
        for (int f = 0; f < 4; f++)
#pragma unroll
            for (int j = 0; j < 8; j++)
#pragma unroll
                for (int q = 0; q < 4; q++) acc[f][j][q] = 0.f;

        const unsigned Abase = As_b + st * 32768;
#pragma unroll
        for (int s = 0; s < 8; s++) {
            unsigned a[4][4];
#pragma unroll
            for (int f = 0; f < 4; f++) {
                int row = warp_m * 64 + f * 16 + li + (grp & 1) * 8;
                int c = s * 2 + (grp >> 1);
                int cks = (c & 8) | ((c & 7) ^ (row & 7));
                LDSM4(a[f][0], a[f][1], a[f][2], a[f][3],
                      Abase + ((row << 4) + cks) * 16);
            }
            unsigned b[4][4];
#pragma unroll
            for (int p = 0; p < 4; p++) {
                int row = s * 16 + li + (grp & 1) * 8;
                int c = warp_n * 8 + p * 2 + (grp >> 1);
                int cks = (c & 24) | ((c & 7) ^ (row & 7));
                LDSM4T(b[p][0], b[p][1], b[p][2], b[p][3],
                       Bs_b + ((row << 5) + cks) * 16);
            }
#pragma unroll
            for (int f = 0; f < 4; f++)
#pragma unroll
                for (int p = 0; p < 4; p++) {
                    MMA16816(acc[f][p * 2],     a[f], b[p][0], b[p][1]);
                    MMA16816(acc[f][p * 2 + 1], a[f], b[p][2], b[p][3]);
                }
        }
        __syncthreads();   // all warps done reading stage st before it is refilled

        // epilogue: + bias, fp16 stores
        const int e0 = t * BM_;
#pragma unroll
        for (int j = 0; j < 8; j++) {
            int cn = warp_n * 64 + j * 8 + (lane & 3) * 2;
#pragma unroll
            for (int f = 0; f < 4; f++) {
                int r = warp_m * 64 + f * 16 + (lane >> 2);
                int e = e0 + r;
                if (e < N_EDGES) {
                    __half2 h = __floats2half2_rn(acc[f][j][0] + bv[j][0],
                                                  acc[f][j][1] + bv[j][1]);
                    *(__half2*)(g_We16 + (size_t)e * 4096 + j0 + cn) = h;
                }
                if (e + 8 < N_EDGES) {
                    __half2 h = __floats2half2_rn(acc[f][j][2] + bv[j][0],
                                                  acc[f][j][3] + bv[j][1]);
                    *(__half2*)(g_We16 + (size_t)(e + 8) * 4096 + j0 + cn) = h;
                }
            }
        }
    }
}

// ---------------- einsum + scatter: warp per edge, streaming uint4 loads ---------------
__global__ void k_einsum(const int* __restrict__ src, const int* __restrict__ dst) {
    __shared__ float xs[8][64];
    int w = threadIdx.x >> 5, t = threadIdx.x & 31;
    int e = (blockIdx.x << 3) + w;              // exactly N_EDGES
    int s = src[e];
    int j2 = t << 1;
    float2 v = *(const float2*)(g_h + s * 64 + j2);
    xs[w][j2] = v.x; xs[w][j2 + 1] = v.y;
    __syncwarp();
    const uint4* __restrict__ W4 = (const uint4*)(g_We16 + (size_t)e * 4096);
    const int cg = t & 7, rg = t >> 3;
    float acc[8];
#pragma unroll
    for (int k = 0; k < 8; k++) acc[k] = 0.f;
#pragma unroll
    for (int i = 0; i < 16; i++) {
        int r = i * 4 + rg;
        uint4 q = __ldcs(W4 + r * 8 + cg);
        float xi = xs[w][r];
        float2 f0 = __half22float2(*(__half2*)&q.x);
        float2 f1 = __half22float2(*(__half2*)&q.y);
        float2 f2 = __half22float2(*(__half2*)&q.z);
        float2 f3 = __half22float2(*(__half2*)&q.w);
        acc[0] = fmaf(xi, f0.x, acc[0]); acc[1] = fmaf(xi, f0.y, acc[1]);
        acc[2] = fmaf(xi, f1.x, acc[2]); acc[3] = fmaf(xi, f1.y, acc[3]);
        acc[4] = fmaf(xi, f2.x, acc[4]); acc[5] = fmaf(xi, f2.y, acc[5]);
        acc[6] = fmaf(xi, f3.x, acc[6]); acc[7] = fmaf(xi, f3.y, acc[7]);
    }
#pragma unroll
    for (int k = 0; k < 8; k++) {
        acc[k] += __shfl_xor_sync(0xffffffffu, acc[k], 8);
        acc[k] += __shfl_xor_sync(0xffffffffu, acc[k], 16);
    }
    int dn = dst[e];
    int k0 = rg * 2;
    int col = cg * 8 + k0;
    atomicAdd(g_agg + dn * 64 + col,     acc[k0]);
    atomicAdd(g_agg + dn * 64 + col + 1, acc[k0 + 1]);
}

// ---------------- GRU cell: smem-cached fp16 weights, 8 warps/block (1 node/warp) -------
__global__ __launch_bounds__(256) void k_gru(const float* __restrict__ bih,
                                             const float* __restrict__ bhh,
                                             const float* __restrict__ cb) {
    __shared__ __half2 sW[64 * 96];   // 24 KB  Wih^T [64][192] as half2 pairs
    __shared__ __half2 sU[64 * 96];   // 24 KB  Whh^T
    const int tid = threadIdx.x;
    {
        const uint4* gw = (const uint4*)g_WihT16;
        const uint4* gu = (const uint4*)g_WhhT16;
        uint4* dw = (uint4*)sW;
        uint4* du = (uint4*)sU;
        for (int i = tid; i < 1536; i += 256) { dw[i] = gw[i]; du[i] = gu[i]; }
    }
    __syncthreads();
    const int w = tid >> 5, t = tid & 31;
    const int n = blockIdx.x * 8 + w;           // exactly N_NODES (grid 1250)
    const int j = t << 1;
    float2 av = *(const float2*)(g_agg + n * 64 + j);
    float2 x2; x2.x = fmaxf(av.x, 0.f); x2.y = fmaxf(av.y, 0.f);
    float2 hv = *(const float2*)(g_h + n * 64 + j);
    *(float2*)(g_agg + n * 64 + j) = *(const float2*)(cb + j);   // reset for next step

    float rx0 = 0.f, rx1 = 0.f, zx0 = 0.f, zx1 = 0.f, nx0 = 0.f, nx1 = 0.f;
    float rh0 = 0.f, rh1 = 0.f, zh0 = 0.f, zh1 = 0.f, nh0 = 0.f, nh1 = 0.f;
#pragma unroll
    for (int i = 0; i < 64; i++) {
        float xi = __shfl_sync(0xffffffffu, (i & 1) ? x2.y : x2.x, i >> 1);
        float hi = __shfl_sync(0xffffffffu, (i & 1) ? hv.y : hv.x, i >> 1);
        float2 wr = __half22float2(sW[i * 96 + t]);
        float2 wz = __half22float2(sW[i * 96 + 32 + t]);
        float2 wn = __half22float2(sW[i * 96 + 64 + t]);
        float2 ur = __half22float2(sU[i * 96 + t]);
        float2 uz = __half22float2(sU[i * 96 + 32 + t]);
        float2 un = __half22float2(sU[i * 96 + 64 + t]);
        rx0 = fmaf(xi, wr.x, rx0); rx1 = fmaf(xi, wr.y, rx1);
        zx0 = fmaf(xi, wz.x, zx0); zx1 = fmaf(xi, wz.y, zx1);
        nx0 = fmaf(xi, wn.x, nx0); nx1 = fmaf(xi, wn.y, nx1);
        rh0 = fmaf(hi, ur.x, rh0); rh1 = fmaf(hi, ur.y, rh1);
        zh0 = fmaf(hi, uz.x, zh0); zh1 = fmaf(hi, uz.y, zh1);
        nh0 = fmaf(hi, un.x, nh0); nh1 = fmaf(hi, un.y, nh1);
    }
    float r0 = sigf(rx0 + bih[j]         + rh0 + bhh[j]);
    float r1 = sigf(rx1 + bih[j + 1]     + rh1 + bhh[j + 1]);
    float z0 = sigf(zx0 + bih[64 + j]    + zh0 + bhh[64 + j]);
    float z1 = sigf(zx1 + bih[64 + j + 1]+ zh1 + bhh[64 + j + 1]);
    float n0 = tanhf(nx0 + bih[128 + j]     + r0 * (nh0 + bhh[128 + j]));
    float n1 = tanhf(nx1 + bih[128 + j + 1] + r1 * (nh1 + bhh[128 + j + 1]));
    float2 o;
    o.x = (1.f - z0) * n0 + z0 * hv.x;
    o.y = (1.f - z1) * n1 + z1 * hv.y;
    *(float2*)(g_h + n * 64 + j) = o;
}

// ---------------- fused Set2Set + head: one block per graph ----------------
__device__ __forceinline__ void lstm_layer(const __half* __restrict__ WT,
                                           const __half* __restrict__ UT,
                                           const float* __restrict__ bih,
                                           const float* __restrict__ bhh,
                                           const float* __restrict__ x, int in_dim,
                                           float* h, float* c, float* g, int tid) {
    float acc = bih[tid] + bhh[tid];
#pragma unroll 4
    for (int i = 0; i < in_dim; i++) acc += x[i] * __half2float(WT[i * 256 + tid]);
#pragma unroll 4
    for (int i = 0; i < 64; i++) acc += h[i] * __half2float(UT[i * 256 + tid]);
    g[tid] = acc;
    __syncthreads();
    if (tid < 64) {
        float ig = sigf(g[tid]);
        float fg = sigf(g[64 + tid]);
        float gg = tanhf(g[128 + tid]);
        float og = sigf(g[192 + tid]);
        float cc = fg * c[tid] + ig * gg;
        c[tid] = cc;
        h[tid] = og * tanhf(cc);
    }
    __syncthreads();
}

__global__ __launch_bounds__(256) void k_set2set(
        const int* __restrict__ gid,
        const float* __restrict__ l0_bih, const float* __restrict__ l0_bhh,
        const float* __restrict__ l12_bih, const float* __restrict__ l12_bhh,
        const float* __restrict__ lin1_W, const float* __restrict__ lin1_b,
        const float* __restrict__ lin2_W, const float* __restrict__ lin2_b,
        float* __restrict__ out) {
    __shared__ float gsh[256];
    __shared__ float hst[3][64], cst[3][64];
    __shared__ float qstar[128];
    __shared__ float m8[8], s8[8];
    __shared__ float r8[8][64];
    __shared__ float t1s[64];
    __shared__ int rng[2];

    const int b = blockIdx.x;
    const int tid = threadIdx.x;
    const int wid = tid >> 5, lane = tid & 31;

    if (tid == 0) {
        int lo = 0, hi = N_NODES;
        while (lo < hi) { int mid = (lo + hi) >> 1; if (gid[mid] < b) lo = mid + 1; else hi = mid; }
        rng[0] = lo;
        lo = 0; hi = N_NODES;
        while (lo < hi) { int mid = (lo + hi) >> 1; if (gid[mid] < b + 1) lo = mid + 1; else hi = mid; }
        rng[1] = lo;
    }
    if (tid < 128) qstar[tid] = 0.f;
    if (tid < 64) {
        hst[0][tid] = 0.f; hst[1][tid] = 0.f; hst[2][tid] = 0.f;
        cst[0][tid] = 0.f; cst[1][tid] = 0.f; cst[2][tid] = 0.f;
    }
    __syncthreads();
    const int ns = rng[0], ne = rng[1];

    for (int step = 0; step < S2S_STEPS; step++) {
        lstm_layer(g_L0ihT, g_L0hhT, l0_bih, l0_bhh, qstar, 128,
                   hst[0], cst[0], gsh, tid);
        lstm_layer(g_L12ihT, g_L12hhT, l12_bih, l12_bhh, hst[0], 64,
                   hst[1], cst[1], gsh, tid);
        lstm_layer(g_L12ihT + 16384, g_L12hhT + 16384, l12_bih + 256, l12_bhh + 256,
                   hst[1], 64, hst[2], cst[2], gsh, tid);
        // attention with streaming softmax; q = hst[2]
        float qa = hst[2][lane], qb = hst[2][32 + lane];
        float m = -INFINITY, ssum = 0.f, r0 = 0.f, r1 = 0.f;
        for (int n = ns + wid; n < ne; n += 8) {
            float o0 = g_h[n * 64 + lane];
            float o1 = g_h[n * 64 + 32 + lane];
            float part = o0 * qa + o1 * qb;
#pragma unroll
            for (int o = 16; o; o >>= 1) part += __shfl_xor_sync(0xffffffffu, part, o);
            if (part > m) {
                float sc = expf(m - part);
                ssum = ssum * sc + 1.f;
                r0 = r0 * sc + o0;
                r1 = r1 * sc + o1;
                m = part;
            } else {
                float wg = expf(part - m);
                ssum += wg;
                r0 += wg * o0;
                r1 += wg * o1;
            }
        }
        if (lane == 0) { m8[wid] = m; s8[wid] = ssum; }
        r8[wid][lane] = r0;
        r8[wid][32 + lane] = r1;
        __syncthreads();
        if (tid < 64) {
            float M = -INFINITY;
#pragma unroll
            for (int w = 0; w < 8; w++) if (s8[w] > 0.f) M = fmaxf(M, m8[w]);
            float S = 0.f, R = 0.f;
#pragma unroll
            for (int w = 0; w < 8; w++) {
                if (s8[w] > 0.f) {
                    float sc = expf(m8[w] - M);
                    S += s8[w] * sc;
                    R += r8[w][tid] * sc;
                }
            }
            qstar[tid] = hst[2][tid];
            qstar[64 + tid] = (S > 0.f) ? (R / S) : 0.f;
        }
        __syncthreads();
    }
    // head: t1 = relu(qstar @ lin1 + b1); out = t1 @ lin2 + b2
    if (tid < 64) {
        float acc = lin1_b[tid];
#pragma unroll 4
        for (int i = 0; i < 128; i++) acc += qstar[i] * lin1_W[i * 64 + tid];
        t1s[tid] = fmaxf(acc, 0.f);
    }
    __syncthreads();
    if (tid < OUT_DIM) {
        float acc = lin2_b[tid];
#pragma unroll 4
        for (int d = 0; d < 64; d++) acc += t1s[d] * lin2_W[d * OUT_DIM + tid];
        out[b * OUT_DIM + tid] = acc;
    }
}

// ---------------- launcher ----------------
extern "C" void kernel_launch(void* const* d_in, const int* in_sizes, int n_in,
                              void* d_out, int out_size) {
    const float* node_feat = (const float*)d_in[0];
    const float* edge_feat = (const float*)d_in[1];
    const int*   src       = (const int*)d_in[2];
    const int*   dst       = (const int*)d_in[3];
    const int*   gid       = (const int*)d_in[4];
    // d_in[5] = num_graphs (unused; B fixed)
    const float* lin0_W = (const float*)d_in[6];
    const float* lin0_b = (const float*)d_in[7];
    const float* em_W1  = (const float*)d_in[8];
    const float* em_b1  = (const float*)d_in[9];
    const float* em_W2  = (const float*)d_in[10];
    const float* em_b2  = (const float*)d_in[11];
    const float* conv_bias = (const float*)d_in[12];
    const float* gru_Wih = (const float*)d_in[13];
    const float* gru_Whh = (const float*)d_in[14];
    const float* gru_bih = (const float*)d_in[15];
    const float* gru_bhh = (const float*)d_in[16];
    const float* l0_Wih = (const float*)d_in[17];
    const float* l0_Whh = (const float*)d_in[18];
    const float* l0_bih = (const float*)d_in[19];
    const float* l0_bhh = (const float*)d_in[20];
    const float* l12_Wih = (const float*)d_in[21];
    const float* l12_Whh = (const float*)d_in[22];
    const float* l12_bih = (const float*)d_in[23];
    const float* l12_bhh = (const float*)d_in[24];
    const float* lin1_W = (const float*)d_in[25];
    const float* lin1_b = (const float*)d_in[26];
    const float* lin2_W = (const float*)d_in[27];
    const float* lin2_b = (const float*)d_in[28];
    float* out = (float*)d_out;

    (void)in_sizes; (void)n_in; (void)out_size;

    // 128 KB dynamic smem for the persistent GEMM (immediate host-side call; capture-safe)
    cudaFuncSetAttribute(k_gemm, cudaFuncAttributeMaxDynamicSharedMemorySize, 131072);

    k_prep<<<128, 256>>>(gru_Wih, gru_Whh, l0_Wih, l0_Whh, l12_Wih, l12_Whh, em_W2);
    k_lin0<<<(N_NODES * 64) / 256, 256>>>(node_feat, lin0_W, lin0_b, conv_bias);
    k_edgehid<<<(N_EDGES * EHID) / 256, 256>>>(edge_feat, em_W1, em_b1);
    k_gemm<<<dim3(DDIM / 256, NSTRIP), 256, 131072>>>(em_b2);

    for (int s = 0; s < MP_STEPS; s++) {
        k_einsum<<<N_EDGES / 8, 256>>>(src, dst);
        k_gru<<<N_NODES / 8, 256>>>(gru_bih, gru_bhh, conv_bias);
    }

    k_set2set<<<NB, 256>>>(gid, l0_bih, l0_bhh, l12_bih, l12_bhh,
                           lin1_W, lin1_b, lin2_W, lin2_b, out);
}